// round 16
// baseline (speedup 1.0000x reference)
#include <cuda_runtime.h>
#include <cuda_fp16.h>
#include <math.h>
#include <stdint.h>

#define BB   2
#define TT   2048
#define HH   16
#define DKD  64
#define DMD  1024
#define MTOT (BB*TT)

// ---------------- device scratch (no allocations allowed) -------------------
__device__ float g_cos[TT*(DKD/2)];
__device__ float g_sin[TT*(DKD/2)];

// fp16 operands (single precision-pass everywhere)
__device__ __half gx_h [MTOT*DMD];
__device__ __half gw_h [4*DMD*DMD];
__device__ __half gctx_h[MTOT*DMD];

__device__ __half g_qh [BB*HH*TT*DKD];     // roped, scale folded
__device__ __half g_kh [BB*HH*TT*DKD];     // roped
__device__ __half g_vh [BB*HH*TT*DKD];     // [B,H,T,64]

// ---------------- helpers -----------------------------------------------------
__device__ __forceinline__ uint32_t smem_u32(const void* p) {
    uint32_t a;
    asm("{ .reg .u64 t; cvta.to.shared.u64 t, %1; cvt.u32.u64 %0, t; }"
        : "=r"(a) : "l"(p));
    return a;
}
__device__ __forceinline__ void cp_async16(uint32_t dst, const void* src) {
    asm volatile("cp.async.cg.shared.global [%0], [%1], 16;"
                 :: "r"(dst), "l"(src) : "memory");
}
#define CP_COMMIT() asm volatile("cp.async.commit_group;" ::: "memory")
#define CP_WAIT(n)  asm volatile("cp.async.wait_group %0;" :: "n"(n) : "memory")

#define LDMX4(r0, r1, r2, r3, addr) \
    asm volatile("ldmatrix.sync.aligned.m8n8.x4.shared.b16 {%0,%1,%2,%3}, [%4];" \
        : "=r"(r0), "=r"(r1), "=r"(r2), "=r"(r3) : "r"(addr))

#define LDMX4T(r0, r1, r2, r3, addr) \
    asm volatile("ldmatrix.sync.aligned.m8n8.x4.trans.shared.b16 {%0,%1,%2,%3}, [%4];" \
        : "=r"(r0), "=r"(r1), "=r"(r2), "=r"(r3) : "r"(addr))

#define MMA_F16(d, a0, a1, a2, a3, b0, b1) \
    asm volatile("mma.sync.aligned.m16n8k16.row.col.f32.f16.f16.f32 " \
        "{%0,%1,%2,%3}, {%4,%5,%6,%7}, {%8,%9}, {%0,%1,%2,%3};" \
        : "+f"((d)[0]), "+f"((d)[1]), "+f"((d)[2]), "+f"((d)[3]) \
        : "r"(a0), "r"(a1), "r"(a2), "r"(a3), "r"(b0), "r"(b1))

__device__ __forceinline__ uint32_t packh2(float x, float y) {
    __half2 h = __floats2half2_rn(x, y);
    return *(uint32_t*)&h;
}

// ---------------- fused prep: x, weights -> fp16 (float4 path); rope tables ----
#define NX4_BLK 4096
#define NW4_BLK 1024
#define PREP_BLOCKS (NX4_BLK + 4*NW4_BLK + 256)

__global__ void prep_kernel(const float4* __restrict__ x,
                            const float4* __restrict__ w0,
                            const float4* __restrict__ w1,
                            const float4* __restrict__ w2,
                            const float4* __restrict__ w3)
{
    const int blk = blockIdx.x;
    if (blk < NX4_BLK) {
        const int i = blk * 256 + threadIdx.x;
        float4 v = x[i];
        uint2 o;
        o.x = packh2(v.x, v.y);
        o.y = packh2(v.z, v.w);
        ((uint2*)gx_h)[i] = o;
    } else if (blk < NX4_BLK + 4 * NW4_BLK) {
        const int wsel = (blk - NX4_BLK) / NW4_BLK;
        const int i = ((blk - NX4_BLK) % NW4_BLK) * 256 + threadIdx.x;
        const float4* w = (wsel == 0) ? w0 : (wsel == 1) ? w1 : (wsel == 2) ? w2 : w3;
        float4 v = w[i];
        uint2 o;
        o.x = packh2(v.x, v.y);
        o.y = packh2(v.z, v.w);
        ((uint2*)(gw_h + ((size_t)wsel << 20)))[i] = o;
    } else {
        const int idx = (blk - NX4_BLK - 4 * NW4_BLK) * 256 + threadIdx.x;
        const int t = idx >> 5;
        const int i = idx & 31;
        double inv = pow(10000.0, -((double)(2 * i)) / 64.0);
        double ang = (double)t * inv;
        g_cos[idx] = (float)cos(ang);
        g_sin[idx] = (float)sin(ang);
    }
}

// ---------------- fp16 single-pass GEMM: C = A * W^T ---------------------------
// CTA tile 128x128, 8 warps (2x4), warp tile 64x32, K chunks of 64, 2 stages.
#define ROWB     144
#define TILE_B   (128 * ROWB)                // 18432
#define STAGE_B  (2 * TILE_B)                // 36864 (A, W)
#define GEMM_SMEM (2 * STAGE_B)              // 73728

template <int QKV>
__global__ void __launch_bounds__(256, 2)
mma_gemm(float* __restrict__ Cout)
{
    extern __shared__ char smem_raw[];
    const uint32_t sb = smem_u32(smem_raw);

    const int tid = threadIdx.x;
    const int wid = tid >> 5;
    const int lid = tid & 31;
    const int n0 = blockIdx.x * 128;
    const int m0 = blockIdx.y * 128;
    const int z  = QKV ? (int)blockIdx.z : 3;

    const __half* Ah = QKV ? gx_h : gctx_h;
    const __half* Wh = gw_h + ((size_t)z << 20);

    const __half* Ah_m = Ah + (size_t)m0 * DMD;
    const __half* Wh_n = Wh + (size_t)n0 * DMD;

    const int llr = tid >> 3;
    const int llc = tid & 7;

    auto load_chunk = [&](int kc, int s) {
        const uint32_t stage = sb + (uint32_t)s * STAGE_B;
        const size_t koff = (size_t)kc * 64 + (size_t)llc * 8;
#pragma unroll
        for (int it = 0; it < 8; ++it) {
            const __half* base = (it < 4) ? Ah_m : Wh_n;
            const int r = (it & 3) * 32 + llr;
            const uint32_t dst = stage + (it < 4 ? 0u : (uint32_t)TILE_B)
                               + (uint32_t)r * ROWB + (uint32_t)llc * 16;
            cp_async16(dst, base + (size_t)r * DMD + koff);
        }
        CP_COMMIT();
    };

    const int wm = wid >> 2;
    const int wn = wid & 3;
    const int lt  = lid >> 3;
    const int lrw = lid & 7;

    const uint32_t a_off = (uint32_t)(wm * 64 + (lt & 1) * 8 + lrw) * ROWB
                         + (uint32_t)(lt >> 1) * 16;
    const uint32_t b_off = (uint32_t)(wn * 32 + (lt & 1) * 8 + lrw) * ROWB
                         + (uint32_t)(lt >> 1) * 16;

    float acc[4][4][4];
#pragma unroll
    for (int i = 0; i < 4; i++)
#pragma unroll
        for (int j = 0; j < 4; j++)
#pragma unroll
            for (int r = 0; r < 4; r++) acc[i][j][r] = 0.0f;

    load_chunk(0, 0);

    for (int c = 0; c < 16; ++c) {
        const int s = c & 1;
        if (c < 15) {
            load_chunk(c + 1, s ^ 1);
            CP_WAIT(1);
        } else {
            CP_WAIT(0);
        }
        __syncthreads();

        const uint32_t stage = sb + (uint32_t)s * STAGE_B;
        const uint32_t ah_base = stage + a_off;
        const uint32_t bh_base = stage + TILE_B + b_off;

#pragma unroll
        for (int kk = 0; kk < 4; ++kk) {
            const uint32_t kb = (uint32_t)kk * 32;
            uint32_t ah[4][4], bh[2][4];
#pragma unroll
            for (int mf = 0; mf < 4; ++mf) {
                LDMX4(ah[mf][0], ah[mf][1], ah[mf][2], ah[mf][3],
                      ah_base + (uint32_t)mf * (16 * ROWB) + kb);
            }
#pragma unroll
            for (int nn = 0; nn < 2; ++nn) {
                LDMX4(bh[nn][0], bh[nn][1], bh[nn][2], bh[nn][3],
                      bh_base + (uint32_t)nn * (16 * ROWB) + kb);
            }
#pragma unroll
            for (int mf = 0; mf < 4; ++mf) {
#pragma unroll
                for (int nf = 0; nf < 4; ++nf) {
                    const int nn = nf >> 1;
                    const int sel = nf & 1;
                    MMA_F16(acc[mf][nf], ah[mf][0], ah[mf][1], ah[mf][2], ah[mf][3],
                            bh[nn][sel], bh[nn][2 + sel]);
                }
            }
        }
        __syncthreads();
    }

    // ---------------- epilogue ----------------
    const int rbase = m0 + wm * 64 + (lid >> 2);
    const int cbase = n0 + wn * 32 + (lid & 3) * 2;

#pragma unroll
    for (int mf = 0; mf < 4; ++mf) {
#pragma unroll
        for (int nf = 0; nf < 4; ++nf) {
#pragma unroll
            for (int half_ = 0; half_ < 2; ++half_) {
                const int m = rbase + mf * 16 + half_ * 8;
                const int n = cbase + nf * 8;
                const float x = acc[mf][nf][half_ * 2 + 0];
                const float y = acc[mf][nf][half_ * 2 + 1];
                if (QKV == 0) {
                    *(float2*)(Cout + (size_t)m * DMD + n) = make_float2(x, y);
                } else {
                    const int b = m >> 11;
                    const int t = m & (TT - 1);
                    const int h = n >> 6;
                    const int d = n & 63;
                    const size_t bh = (size_t)(b * HH + h);
                    const size_t idx = (bh * TT + t) * DKD + d;
                    if (z < 2) {
                        const float cs = g_cos[t * 32 + (d >> 1)];
                        const float sn = g_sin[t * 32 + (d >> 1)];
                        float rx = x * cs - y * sn;
                        float ry = x * sn + y * cs;
                        if (z == 0) {
                            *(uint32_t*)(g_qh + idx) = packh2(rx * 0.125f, ry * 0.125f);
                        } else {
                            *(uint32_t*)(g_kh + idx) = packh2(rx, ry);
                        }
                    } else {
                        *(uint32_t*)(g_vh + idx) = packh2(x, y);
                    }
                }
            }
        }
    }
}

// ---------------- tensor-core causal flash attention (fp16 single-pass) --------
// V via ldmatrix.trans; fully-masked diagonal sub-blocks skipped (warp-uniform).
#define AROWB 144
#define ATILE (64 * AROWB)                 // 9216
#define ATT_SMEM (ATILE + 4 * ATILE)       // 46080: Q + 2 stages * (K, V)

__global__ void __launch_bounds__(128)
attn_kernel()
{
    extern __shared__ char smem_raw[];
    const uint32_t sb = smem_u32(smem_raw);
    const uint32_t stages = sb + ATILE;

    const int h   = blockIdx.x;
    const int b   = blockIdx.y;
    const int qt  = (int)(gridDim.z - 1 - blockIdx.z);   // heavy tiles first
    const int tid = threadIdx.x;
    const int wq  = tid >> 5;
    const int lid = tid & 31;

    const size_t bh = (size_t)(b * HH + h);
    const __half* qh_g = g_qh + (bh * TT + (size_t)qt * 64) * DKD;
    const __half* kh_g = g_kh + bh * TT * DKD;
    const __half* vh_g = g_vh + bh * TT * DKD;

#pragma unroll
    for (int i = 0; i < 4; ++i) {
        int cid = i * 128 + tid;
        int r = cid >> 3, c = cid & 7;
        cp_async16(sb + (uint32_t)r * AROWB + (uint32_t)c * 16,
                   qh_g + (size_t)r * DKD + c * 8);
    }
    CP_COMMIT();

    auto load_kv = [&](int kt, int s) {
        const uint32_t stage = stages + (uint32_t)s * (2 * ATILE);
#pragma unroll
        for (int i = 0; i < 4; ++i) {
            int cid = i * 128 + tid;
            int r = cid >> 3, c = cid & 7;
            const uint32_t so = (uint32_t)r * AROWB + (uint32_t)c * 16;
            const size_t kk = (size_t)(kt * 64 + r) * DKD + c * 8;
            cp_async16(stage + so,         kh_g + kk);
            cp_async16(stage + ATILE + so, vh_g + kk);
        }
        CP_COMMIT();
    };

    const int lt  = lid >> 3;
    const int lrw = lid & 7;
    const uint32_t a_off = (uint32_t)(wq * 16 + (lt & 1) * 8 + lrw) * AROWB
                         + (uint32_t)(lt >> 1) * 16;
    uint32_t bn_off[4];
#pragma unroll
    for (int nn = 0; nn < 4; ++nn)
        bn_off[nn] = (uint32_t)(nn * 16 + (lt & 1) * 8 + lrw) * AROWB
                   + (uint32_t)(lt >> 1) * 16;
    const uint32_t v_off = (uint32_t)((lt >> 1) * 8 + lrw) * AROWB
                         + (uint32_t)(lt & 1) * 16;

    load_kv(0, 0);

    CP_WAIT(1);
    __syncthreads();
    uint32_t qf[4][4];
#pragma unroll
    for (int ks = 0; ks < 4; ++ks) {
        LDMX4(qf[ks][0], qf[ks][1], qf[ks][2], qf[ks][3], sb + a_off + ks * 32);
    }

    float O[8][4];
#pragma unroll
    for (int i = 0; i < 8; ++i)
#pragma unroll
        for (int j = 0; j < 4; ++j) O[i][j] = 0.0f;
    float m0v = -1e30f, m1v = -1e30f, l0 = 0.0f, l1 = 0.0f;

    for (int kt = 0; kt <= qt; ++kt) {
        const int s = kt & 1;
        if (kt < qt) {
            load_kv(kt + 1, s ^ 1);
            CP_WAIT(1);
        } else {
            CP_WAIT(0);
        }
        __syncthreads();

        const uint32_t stage = stages + (uint32_t)s * (2 * ATILE);
        // in the diagonal tile, n/k sub-blocks beyond this warp's rows are
        // fully masked (QK) or multiply exact zeros (PV) -> skip them.
        const int nnmax = (kt == qt) ? wq : 3;

        // ---- S = Q K^T (single pass) ----
        float S[8][4];
#pragma unroll
        for (int i = 0; i < 8; ++i)
#pragma unroll
            for (int j = 0; j < 4; ++j) S[i][j] = 0.0f;

#pragma unroll
        for (int ks = 0; ks < 4; ++ks) {
            uint32_t kh[4][4];
#pragma unroll
            for (int nn = 0; nn < 4; ++nn) {
                if (nn > nnmax) continue;      // warp-uniform skip
                LDMX4(kh[nn][0], kh[nn][1], kh[nn][2], kh[nn][3],
                      stage + bn_off[nn] + ks * 32);
            }
#pragma unroll
            for (int nf = 0; nf < 8; ++nf) {
                const int nn = nf >> 1;
                const int sel = nf & 1;
                if (nn > nnmax) continue;
                MMA_F16(S[nf], qf[ks][0], qf[ks][1], qf[ks][2], qf[ks][3],
                        kh[nn][sel], kh[nn][2 + sel]);
            }
        }

        // ---- causal mask on diagonal tile (covers skipped blocks too) ----
        if (kt == qt) {
            const int row0 = wq * 16 + (lid >> 2);
            const int colb = (lid & 3) * 2;
#pragma unroll
            for (int nf = 0; nf < 8; ++nf) {
                const int c0 = nf * 8 + colb;
                if (c0     > row0)     S[nf][0] = -1e30f;
                if (c0 + 1 > row0)     S[nf][1] = -1e30f;
                if (c0     > row0 + 8) S[nf][2] = -1e30f;
                if (c0 + 1 > row0 + 8) S[nf][3] = -1e30f;
            }
        }

        // ---- online softmax ----
        float r0 = -1e30f, r1 = -1e30f;
#pragma unroll
        for (int nf = 0; nf < 8; ++nf) {
            r0 = fmaxf(r0, fmaxf(S[nf][0], S[nf][1]));
            r1 = fmaxf(r1, fmaxf(S[nf][2], S[nf][3]));
        }
        r0 = fmaxf(r0, __shfl_xor_sync(0xffffffffu, r0, 1));
        r0 = fmaxf(r0, __shfl_xor_sync(0xffffffffu, r0, 2));
        r1 = fmaxf(r1, __shfl_xor_sync(0xffffffffu, r1, 1));
        r1 = fmaxf(r1, __shfl_xor_sync(0xffffffffu, r1, 2));

        const float nm0 = fmaxf(m0v, r0);
        const float nm1 = fmaxf(m1v, r1);
        const float a0 = __expf(m0v - nm0);
        const float a1 = __expf(m1v - nm1);
        m0v = nm0; m1v = nm1;

        float rs0 = 0.0f, rs1 = 0.0f;
#pragma unroll
        for (int nf = 0; nf < 8; ++nf) {
            S[nf][0] = __expf(S[nf][0] - m0v);
            S[nf][1] = __expf(S[nf][1] - m0v);
            S[nf][2] = __expf(S[nf][2] - m1v);
            S[nf][3] = __expf(S[nf][3] - m1v);
            rs0 += S[nf][0] + S[nf][1];
            rs1 += S[nf][2] + S[nf][3];
        }
        rs0 += __shfl_xor_sync(0xffffffffu, rs0, 1);
        rs0 += __shfl_xor_sync(0xffffffffu, rs0, 2);
        rs1 += __shfl_xor_sync(0xffffffffu, rs1, 1);
        rs1 += __shfl_xor_sync(0xffffffffu, rs1, 2);
        l0 = l0 * a0 + rs0;
        l1 = l1 * a1 + rs1;

#pragma unroll
        for (int nf = 0; nf < 8; ++nf) {
            O[nf][0] *= a0; O[nf][1] *= a0;
            O[nf][2] *= a1; O[nf][3] *= a1;
        }

        // ---- PV (single pass, V via ldmatrix.trans) ----
#pragma unroll
        for (int kb2 = 0; kb2 < 4; ++kb2) {
            if (kb2 > nnmax) continue;         // P==0 for these keys (diag tile)
            uint32_t ph[4];
            ph[0] = packh2(S[2 * kb2][0],     S[2 * kb2][1]);
            ph[1] = packh2(S[2 * kb2][2],     S[2 * kb2][3]);
            ph[2] = packh2(S[2 * kb2 + 1][0], S[2 * kb2 + 1][1]);
            ph[3] = packh2(S[2 * kb2 + 1][2], S[2 * kb2 + 1][3]);

            const uint32_t vrow = stage + ATILE + v_off + (uint32_t)kb2 * (16 * AROWB);
            uint32_t vh[4][4];
#pragma unroll
            for (int nn = 0; nn < 4; ++nn) {
                LDMX4T(vh[nn][0], vh[nn][1], vh[nn][2], vh[nn][3],
                       vrow + (uint32_t)nn * 32);
            }
#pragma unroll
            for (int nf = 0; nf < 8; ++nf) {
                const int nn = nf >> 1;
                const int sel = nf & 1;
                MMA_F16(O[nf], ph[0], ph[1], ph[2], ph[3],
                        vh[nn][sel], vh[nn][2 + sel]);
            }
        }
        __syncthreads();
    }

    // ---- epilogue: ctx fp16 ----
    const float i0 = 1.0f / l0;
    const float i1 = 1.0f / l1;
    const int q0 = qt * 64 + wq * 16 + (lid >> 2);
    const int colb = (lid & 3) * 2;
#pragma unroll
    for (int nf = 0; nf < 8; ++nf) {
        const int d = nf * 8 + colb;
        size_t idx = ((size_t)b * TT + q0) * DMD + h * DKD + d;
        *(uint32_t*)(gctx_h + idx) = packh2(O[nf][0] * i0, O[nf][1] * i0);
        idx += (size_t)8 * DMD;
        *(uint32_t*)(gctx_h + idx) = packh2(O[nf][2] * i1, O[nf][3] * i1);
    }
}

// ---------------- launch ---------------------------------------------------------
extern "C" void kernel_launch(void* const* d_in, const int* in_sizes, int n_in,
                              void* d_out, int out_size)
{
    const float* x   = (const float*)d_in[0];
    const float* w_q = (const float*)d_in[1];
    const float* w_k = (const float*)d_in[2];
    const float* w_v = (const float*)d_in[3];
    const float* w_o = (const float*)d_in[4];
    float* out = (float*)d_out;

    static int configured = 0;
    if (!configured) {
        cudaFuncSetAttribute(mma_gemm<1>, cudaFuncAttributeMaxDynamicSharedMemorySize, GEMM_SMEM);
        cudaFuncSetAttribute(mma_gemm<0>, cudaFuncAttributeMaxDynamicSharedMemorySize, GEMM_SMEM);
        cudaFuncSetAttribute(attn_kernel, cudaFuncAttributeMaxDynamicSharedMemorySize, ATT_SMEM);
        configured = 1;
    }

    prep_kernel<<<PREP_BLOCKS, 256>>>((const float4*)x, (const float4*)w_q,
                                      (const float4*)w_k, (const float4*)w_v,
                                      (const float4*)w_o);

    mma_gemm<1><<<dim3(DMD / 128, MTOT / 128, 3), 256, GEMM_SMEM>>>(nullptr);

    attn_kernel<<<dim3(HH, BB, TT / 64), 128, ATT_SMEM>>>();

    mma_gemm<0><<<dim3(DMD / 128, MTOT / 128, 1), 256, GEMM_SMEM>>>(out);
}

// round 17
// speedup vs baseline: 1.0332x; 1.0332x over previous
#include <cuda_runtime.h>
#include <cuda_fp16.h>
#include <math.h>
#include <stdint.h>

#define BB   2
#define TT   2048
#define HH   16
#define DKD  64
#define DMD  1024
#define MTOT (BB*TT)

// ---------------- device scratch (no allocations allowed) -------------------
__device__ float g_cos[TT*(DKD/2)];
__device__ float g_sin[TT*(DKD/2)];

// fp16 operands (single precision-pass everywhere)
__device__ __half gx_h [MTOT*DMD];
__device__ __half gw_h [4*DMD*DMD];
__device__ __half gctx_h[MTOT*DMD];

__device__ __half g_qh [BB*HH*TT*DKD];     // roped, scale folded
__device__ __half g_kh [BB*HH*TT*DKD];     // roped
__device__ __half g_vh [BB*HH*TT*DKD];     // [B,H,T,64] (NOT transposed)

// ---------------- helpers -----------------------------------------------------
__device__ __forceinline__ uint32_t smem_u32(const void* p) {
    uint32_t a;
    asm("{ .reg .u64 t; cvta.to.shared.u64 t, %1; cvt.u32.u64 %0, t; }"
        : "=r"(a) : "l"(p));
    return a;
}
__device__ __forceinline__ void cp_async16(uint32_t dst, const void* src) {
    asm volatile("cp.async.cg.shared.global [%0], [%1], 16;"
                 :: "r"(dst), "l"(src) : "memory");
}
#define CP_COMMIT() asm volatile("cp.async.commit_group;" ::: "memory")
#define CP_WAIT(n)  asm volatile("cp.async.wait_group %0;" :: "n"(n) : "memory")

#define LDMX4(r0, r1, r2, r3, addr) \
    asm volatile("ldmatrix.sync.aligned.m8n8.x4.shared.b16 {%0,%1,%2,%3}, [%4];" \
        : "=r"(r0), "=r"(r1), "=r"(r2), "=r"(r3) : "r"(addr))

#define LDMX4T(r0, r1, r2, r3, addr) \
    asm volatile("ldmatrix.sync.aligned.m8n8.x4.trans.shared.b16 {%0,%1,%2,%3}, [%4];" \
        : "=r"(r0), "=r"(r1), "=r"(r2), "=r"(r3) : "r"(addr))

#define MMA_F16(d, a0, a1, a2, a3, b0, b1) \
    asm volatile("mma.sync.aligned.m16n8k16.row.col.f32.f16.f16.f32 " \
        "{%0,%1,%2,%3}, {%4,%5,%6,%7}, {%8,%9}, {%0,%1,%2,%3};" \
        : "+f"((d)[0]), "+f"((d)[1]), "+f"((d)[2]), "+f"((d)[3]) \
        : "r"(a0), "r"(a1), "r"(a2), "r"(a3), "r"(b0), "r"(b1))

__device__ __forceinline__ uint32_t packh2(float x, float y) {
    __half2 h = __floats2half2_rn(x, y);
    return *(uint32_t*)&h;
}

// ---------------- fused prep: x, weights -> fp16 (float4 path); rope tables ----
#define NX4_BLK 4096
#define NW4_BLK 1024
#define PREP_BLOCKS (NX4_BLK + 4*NW4_BLK + 256)

__global__ void prep_kernel(const float4* __restrict__ x,
                            const float4* __restrict__ w0,
                            const float4* __restrict__ w1,
                            const float4* __restrict__ w2,
                            const float4* __restrict__ w3)
{
    const int blk = blockIdx.x;
    if (blk < NX4_BLK) {
        const int i = blk * 256 + threadIdx.x;
        float4 v = x[i];
        uint2 o;
        o.x = packh2(v.x, v.y);
        o.y = packh2(v.z, v.w);
        ((uint2*)gx_h)[i] = o;
    } else if (blk < NX4_BLK + 4 * NW4_BLK) {
        const int wsel = (blk - NX4_BLK) / NW4_BLK;
        const int i = ((blk - NX4_BLK) % NW4_BLK) * 256 + threadIdx.x;
        const float4* w = (wsel == 0) ? w0 : (wsel == 1) ? w1 : (wsel == 2) ? w2 : w3;
        float4 v = w[i];
        uint2 o;
        o.x = packh2(v.x, v.y);
        o.y = packh2(v.z, v.w);
        ((uint2*)(gw_h + ((size_t)wsel << 20)))[i] = o;
    } else {
        const int idx = (blk - NX4_BLK - 4 * NW4_BLK) * 256 + threadIdx.x;
        const int t = idx >> 5;
        const int i = idx & 31;
        double inv = pow(10000.0, -((double)(2 * i)) / 64.0);
        double ang = (double)t * inv;
        g_cos[idx] = (float)cos(ang);
        g_sin[idx] = (float)sin(ang);
    }
}

// ---------------- fp16 single-pass GEMM: C = A * W^T ---------------------------
// CTA tile 128x128, 8 warps (2x4), warp tile 64x32, K chunks of 64, 2 stages.
#define ROWB     144
#define TILE_B   (128 * ROWB)                // 18432
#define STAGE_B  (2 * TILE_B)                // 36864 (A, W)
#define GEMM_SMEM (2 * STAGE_B)              // 73728

template <int QKV>
__global__ void __launch_bounds__(256, 2)
mma_gemm(float* __restrict__ Cout)
{
    extern __shared__ char smem_raw[];
    const uint32_t sb = smem_u32(smem_raw);

    const int tid = threadIdx.x;
    const int wid = tid >> 5;
    const int lid = tid & 31;
    const int n0 = blockIdx.x * 128;
    const int m0 = blockIdx.y * 128;
    const int z  = QKV ? (int)blockIdx.z : 3;

    const __half* Ah = QKV ? gx_h : gctx_h;
    const __half* Wh = gw_h + ((size_t)z << 20);

    const __half* Ah_m = Ah + (size_t)m0 * DMD;
    const __half* Wh_n = Wh + (size_t)n0 * DMD;

    const int llr = tid >> 3;
    const int llc = tid & 7;

    auto load_chunk = [&](int kc, int s) {
        const uint32_t stage = sb + (uint32_t)s * STAGE_B;
        const size_t koff = (size_t)kc * 64 + (size_t)llc * 8;
#pragma unroll
        for (int it = 0; it < 8; ++it) {
            const __half* base = (it < 4) ? Ah_m : Wh_n;
            const int r = (it & 3) * 32 + llr;
            const uint32_t dst = stage + (it < 4 ? 0u : (uint32_t)TILE_B)
                               + (uint32_t)r * ROWB + (uint32_t)llc * 16;
            cp_async16(dst, base + (size_t)r * DMD + koff);
        }
        CP_COMMIT();
    };

    const int wm = wid >> 2;
    const int wn = wid & 3;
    const int lt  = lid >> 3;
    const int lrw = lid & 7;

    const uint32_t a_off = (uint32_t)(wm * 64 + (lt & 1) * 8 + lrw) * ROWB
                         + (uint32_t)(lt >> 1) * 16;
    const uint32_t b_off = (uint32_t)(wn * 32 + (lt & 1) * 8 + lrw) * ROWB
                         + (uint32_t)(lt >> 1) * 16;

    float acc[4][4][4];
#pragma unroll
    for (int i = 0; i < 4; i++)
#pragma unroll
        for (int j = 0; j < 4; j++)
#pragma unroll
            for (int r = 0; r < 4; r++) acc[i][j][r] = 0.0f;

    load_chunk(0, 0);

    for (int c = 0; c < 16; ++c) {
        const int s = c & 1;
        if (c < 15) {
            load_chunk(c + 1, s ^ 1);
            CP_WAIT(1);
        } else {
            CP_WAIT(0);
        }
        __syncthreads();

        const uint32_t stage = sb + (uint32_t)s * STAGE_B;
        const uint32_t ah_base = stage + a_off;
        const uint32_t bh_base = stage + TILE_B + b_off;

#pragma unroll
        for (int kk = 0; kk < 4; ++kk) {
            const uint32_t kb = (uint32_t)kk * 32;
            uint32_t ah[4][4], bh[2][4];
#pragma unroll
            for (int mf = 0; mf < 4; ++mf) {
                LDMX4(ah[mf][0], ah[mf][1], ah[mf][2], ah[mf][3],
                      ah_base + (uint32_t)mf * (16 * ROWB) + kb);
            }
#pragma unroll
            for (int nn = 0; nn < 2; ++nn) {
                LDMX4(bh[nn][0], bh[nn][1], bh[nn][2], bh[nn][3],
                      bh_base + (uint32_t)nn * (16 * ROWB) + kb);
            }
#pragma unroll
            for (int mf = 0; mf < 4; ++mf) {
#pragma unroll
                for (int nf = 0; nf < 4; ++nf) {
                    const int nn = nf >> 1;
                    const int sel = nf & 1;
                    MMA_F16(acc[mf][nf], ah[mf][0], ah[mf][1], ah[mf][2], ah[mf][3],
                            bh[nn][sel], bh[nn][2 + sel]);
                }
            }
        }
        __syncthreads();
    }

    // ---------------- epilogue ----------------
    const int rbase = m0 + wm * 64 + (lid >> 2);
    const int cbase = n0 + wn * 32 + (lid & 3) * 2;

#pragma unroll
    for (int mf = 0; mf < 4; ++mf) {
#pragma unroll
        for (int nf = 0; nf < 4; ++nf) {
#pragma unroll
            for (int half_ = 0; half_ < 2; ++half_) {
                const int m = rbase + mf * 16 + half_ * 8;
                const int n = cbase + nf * 8;
                const float x = acc[mf][nf][half_ * 2 + 0];
                const float y = acc[mf][nf][half_ * 2 + 1];
                if (QKV == 0) {
                    *(float2*)(Cout + (size_t)m * DMD + n) = make_float2(x, y);
                } else {
                    const int b = m >> 11;
                    const int t = m & (TT - 1);
                    const int h = n >> 6;
                    const int d = n & 63;
                    const size_t bh = (size_t)(b * HH + h);
                    const size_t idx = (bh * TT + t) * DKD + d;
                    if (z < 2) {
                        const float cs = g_cos[t * 32 + (d >> 1)];
                        const float sn = g_sin[t * 32 + (d >> 1)];
                        float rx = x * cs - y * sn;
                        float ry = x * sn + y * cs;
                        if (z == 0) {
                            *(uint32_t*)(g_qh + idx) = packh2(rx * 0.125f, ry * 0.125f);
                        } else {
                            *(uint32_t*)(g_kh + idx) = packh2(rx, ry);
                        }
                    } else {
                        // V: coalesced, same layout as K (no transpose)
                        *(uint32_t*)(g_vh + idx) = packh2(x, y);
                    }
                }
            }
        }
    }
}

// ---------------- tensor-core causal flash attention (fp16 single-pass) --------
// V loaded from row-major [key, d] tile via ldmatrix.trans (register-identical
// fragments to a transposed-layout load).
#define AROWB 144
#define ATILE (64 * AROWB)                 // 9216
#define ATT_SMEM (ATILE + 4 * ATILE)       // 46080: Q + 2 stages * (K, V)

__global__ void __launch_bounds__(128)
attn_kernel()
{
    extern __shared__ char smem_raw[];
    const uint32_t sb = smem_u32(smem_raw);
    const uint32_t stages = sb + ATILE;

    const int h   = blockIdx.x;
    const int b   = blockIdx.y;
    const int qt  = (int)(gridDim.z - 1 - blockIdx.z);   // heavy tiles first
    const int tid = threadIdx.x;
    const int wq  = tid >> 5;
    const int lid = tid & 31;

    const size_t bh = (size_t)(b * HH + h);
    const __half* qh_g = g_qh + (bh * TT + (size_t)qt * 64) * DKD;
    const __half* kh_g = g_kh + bh * TT * DKD;
    const __half* vh_g = g_vh + bh * TT * DKD;

#pragma unroll
    for (int i = 0; i < 4; ++i) {
        int cid = i * 128 + tid;
        int r = cid >> 3, c = cid & 7;
        cp_async16(sb + (uint32_t)r * AROWB + (uint32_t)c * 16,
                   qh_g + (size_t)r * DKD + c * 8);
    }
    CP_COMMIT();

    auto load_kv = [&](int kt, int s) {
        const uint32_t stage = stages + (uint32_t)s * (2 * ATILE);
#pragma unroll
        for (int i = 0; i < 4; ++i) {
            int cid = i * 128 + tid;
            int r = cid >> 3, c = cid & 7;
            const uint32_t so = (uint32_t)r * AROWB + (uint32_t)c * 16;
            const size_t kk = (size_t)(kt * 64 + r) * DKD + c * 8;
            cp_async16(stage + so,         kh_g + kk);
            cp_async16(stage + ATILE + so, vh_g + kk);
        }
        CP_COMMIT();
    };

    const int lt  = lid >> 3;
    const int lrw = lid & 7;
    const uint32_t a_off = (uint32_t)(wq * 16 + (lt & 1) * 8 + lrw) * AROWB
                         + (uint32_t)(lt >> 1) * 16;
    uint32_t bn_off[4];
#pragma unroll
    for (int nn = 0; nn < 4; ++nn)
        bn_off[nn] = (uint32_t)(nn * 16 + (lt & 1) * 8 + lrw) * AROWB
                   + (uint32_t)(lt >> 1) * 16;
    // trans-V addressing: row = k-group + (lt>>1)*8 + lrw ; col bytes = (lt&1)*16
    const uint32_t v_off = (uint32_t)((lt >> 1) * 8 + lrw) * AROWB
                         + (uint32_t)(lt & 1) * 16;

    load_kv(0, 0);

    CP_WAIT(1);
    __syncthreads();
    uint32_t qf[4][4];
#pragma unroll
    for (int ks = 0; ks < 4; ++ks) {
        LDMX4(qf[ks][0], qf[ks][1], qf[ks][2], qf[ks][3], sb + a_off + ks * 32);
    }

    float O[8][4];
#pragma unroll
    for (int i = 0; i < 8; ++i)
#pragma unroll
        for (int j = 0; j < 4; ++j) O[i][j] = 0.0f;
    float m0v = -1e30f, m1v = -1e30f, l0 = 0.0f, l1 = 0.0f;

    for (int kt = 0; kt <= qt; ++kt) {
        const int s = kt & 1;
        if (kt < qt) {
            load_kv(kt + 1, s ^ 1);
            CP_WAIT(1);
        } else {
            CP_WAIT(0);
        }
        __syncthreads();

        const uint32_t stage = stages + (uint32_t)s * (2 * ATILE);

        // ---- S = Q K^T (single pass) ----
        float S[8][4];
#pragma unroll
        for (int i = 0; i < 8; ++i)
#pragma unroll
            for (int j = 0; j < 4; ++j) S[i][j] = 0.0f;

#pragma unroll
        for (int ks = 0; ks < 4; ++ks) {
            uint32_t kh[4][4];
#pragma unroll
            for (int nn = 0; nn < 4; ++nn) {
                LDMX4(kh[nn][0], kh[nn][1], kh[nn][2], kh[nn][3],
                      stage + bn_off[nn] + ks * 32);
            }
#pragma unroll
            for (int nf = 0; nf < 8; ++nf) {
                const int nn = nf >> 1;
                const int sel = nf & 1;
                MMA_F16(S[nf], qf[ks][0], qf[ks][1], qf[ks][2], qf[ks][3],
                        kh[nn][sel], kh[nn][2 + sel]);
            }
        }

        // ---- causal mask on diagonal tile ----
        if (kt == qt) {
            const int row0 = wq * 16 + (lid >> 2);
            const int colb = (lid & 3) * 2;
#pragma unroll
            for (int nf = 0; nf < 8; ++nf) {
                const int c0 = nf * 8 + colb;
                if (c0     > row0)     S[nf][0] = -1e30f;
                if (c0 + 1 > row0)     S[nf][1] = -1e30f;
                if (c0     > row0 + 8) S[nf][2] = -1e30f;
                if (c0 + 1 > row0 + 8) S[nf][3] = -1e30f;
            }
        }

        // ---- online softmax ----
        float r0 = -1e30f, r1 = -1e30f;
#pragma unroll
        for (int nf = 0; nf < 8; ++nf) {
            r0 = fmaxf(r0, fmaxf(S[nf][0], S[nf][1]));
            r1 = fmaxf(r1, fmaxf(S[nf][2], S[nf][3]));
        }
        r0 = fmaxf(r0, __shfl_xor_sync(0xffffffffu, r0, 1));
        r0 = fmaxf(r0, __shfl_xor_sync(0xffffffffu, r0, 2));
        r1 = fmaxf(r1, __shfl_xor_sync(0xffffffffu, r1, 1));
        r1 = fmaxf(r1, __shfl_xor_sync(0xffffffffu, r1, 2));

        const float nm0 = fmaxf(m0v, r0);
        const float nm1 = fmaxf(m1v, r1);
        const float a0 = __expf(m0v - nm0);
        const float a1 = __expf(m1v - nm1);
        m0v = nm0; m1v = nm1;

        float rs0 = 0.0f, rs1 = 0.0f;
#pragma unroll
        for (int nf = 0; nf < 8; ++nf) {
            S[nf][0] = __expf(S[nf][0] - m0v);
            S[nf][1] = __expf(S[nf][1] - m0v);
            S[nf][2] = __expf(S[nf][2] - m1v);
            S[nf][3] = __expf(S[nf][3] - m1v);
            rs0 += S[nf][0] + S[nf][1];
            rs1 += S[nf][2] + S[nf][3];
        }
        rs0 += __shfl_xor_sync(0xffffffffu, rs0, 1);
        rs0 += __shfl_xor_sync(0xffffffffu, rs0, 2);
        rs1 += __shfl_xor_sync(0xffffffffu, rs1, 1);
        rs1 += __shfl_xor_sync(0xffffffffu, rs1, 2);
        l0 = l0 * a0 + rs0;
        l1 = l1 * a1 + rs1;

#pragma unroll
        for (int nf = 0; nf < 8; ++nf) {
            O[nf][0] *= a0; O[nf][1] *= a0;
            O[nf][2] *= a1; O[nf][3] *= a1;
        }

        // ---- PV (single pass, V via ldmatrix.trans from [key,d] tile) ----
#pragma unroll
        for (int kb2 = 0; kb2 < 4; ++kb2) {
            uint32_t ph[4];
            ph[0] = packh2(S[2 * kb2][0],     S[2 * kb2][1]);
            ph[1] = packh2(S[2 * kb2][2],     S[2 * kb2][3]);
            ph[2] = packh2(S[2 * kb2 + 1][0], S[2 * kb2 + 1][1]);
            ph[3] = packh2(S[2 * kb2 + 1][2], S[2 * kb2 + 1][3]);

            const uint32_t vrow = stage + ATILE + v_off + (uint32_t)kb2 * (16 * AROWB);
            uint32_t vh[4][4];
#pragma unroll
            for (int nn = 0; nn < 4; ++nn) {
                LDMX4T(vh[nn][0], vh[nn][1], vh[nn][2], vh[nn][3],
                       vrow + (uint32_t)nn * 32);
            }
#pragma unroll
            for (int nf = 0; nf < 8; ++nf) {
                const int nn = nf >> 1;
                const int sel = nf & 1;
                MMA_F16(O[nf], ph[0], ph[1], ph[2], ph[3],
                        vh[nn][sel], vh[nn][2 + sel]);
            }
        }
        __syncthreads();
    }

    // ---- epilogue: ctx fp16 ----
    const float i0 = 1.0f / l0;
    const float i1 = 1.0f / l1;
    const int q0 = qt * 64 + wq * 16 + (lid >> 2);
    const int colb = (lid & 3) * 2;
#pragma unroll
    for (int nf = 0; nf < 8; ++nf) {
        const int d = nf * 8 + colb;
        size_t idx = ((size_t)b * TT + q0) * DMD + h * DKD + d;
        *(uint32_t*)(gctx_h + idx) = packh2(O[nf][0] * i0, O[nf][1] * i0);
        idx += (size_t)8 * DMD;
        *(uint32_t*)(gctx_h + idx) = packh2(O[nf][2] * i1, O[nf][3] * i1);
    }
}

// ---------------- launch ---------------------------------------------------------
extern "C" void kernel_launch(void* const* d_in, const int* in_sizes, int n_in,
                              void* d_out, int out_size)
{
    const float* x   = (const float*)d_in[0];
    const float* w_q = (const float*)d_in[1];
    const float* w_k = (const float*)d_in[2];
    const float* w_v = (const float*)d_in[3];
    const float* w_o = (const float*)d_in[4];
    float* out = (float*)d_out;

    static int configured = 0;
    if (!configured) {
        cudaFuncSetAttribute(mma_gemm<1>, cudaFuncAttributeMaxDynamicSharedMemorySize, GEMM_SMEM);
        cudaFuncSetAttribute(mma_gemm<0>, cudaFuncAttributeMaxDynamicSharedMemorySize, GEMM_SMEM);
        cudaFuncSetAttribute(attn_kernel, cudaFuncAttributeMaxDynamicSharedMemorySize, ATT_SMEM);
        configured = 1;
    }

    prep_kernel<<<PREP_BLOCKS, 256>>>((const float4*)x, (const float4*)w_q,
                                      (const float4*)w_k, (const float4*)w_v,
                                      (const float4*)w_o);

    mma_gemm<1><<<dim3(DMD / 128, MTOT / 128, 3), 256, GEMM_SMEM>>>(nullptr);

    attn_kernel<<<dim3(HH, BB, TT / 64), 128, ATT_SMEM>>>();

    mma_gemm<0><<<dim3(DMD / 128, MTOT / 128, 1), 256, GEMM_SMEM>>>(out);
}